// round 12
// baseline (speedup 1.0000x reference)
#include <cuda_runtime.h>
#include <cstddef>

// Inputs (metadata order):
//  0: transformation  float32  (4,4)
//  1: src_points      float32  (N,4)
//  2: tar_points      float32  (N,4)
//  3: covs_src        float32  (N,4,4)
//  4: covs_tar        float32  (N,4,4)
//  5: nearest_indices int32    (N,)
// Output: scalar float = 0.5 * mean(maha)
//
// Persistent grid-stride variant of the R1 roofline kernel: grid sized to
// exactly one wave (152 SMs x 8 CTAs), each thread loops over ~6.4 points.
// Removes the ~5.6 wave transitions of the 7813-CTA launch, amortizes the
// T broadcast load, and gives the compiler cross-iteration load/compute
// overlap without R10's occupancy loss.

__global__ void gicp_zero_out(float* out) {
    if (blockIdx.x == 0 && threadIdx.x == 0) out[0] = 0.0f;
}

__global__ __launch_bounds__(256) void gicp_kernel(
    const float*  __restrict__ T,         // 16 floats
    const float4* __restrict__ src,       // N rows (x,y,z,1)
    const float4* __restrict__ tar,       // N rows
    const float4* __restrict__ covs_src,  // N * 4 rows
    const float4* __restrict__ covs_tar,  // N * 4 rows
    const int*    __restrict__ idx,       // N
    float*        __restrict__ out,
    int n, float scale)
{
    // Broadcast load of the 4x4 transformation, once per thread.
    float t[16];
    #pragma unroll
    for (int k = 0; k < 16; ++k) t[k] = __ldg(T + k);

    const int stride = gridDim.x * blockDim.x;
    float acc = 0.0f;

    for (int i = blockIdx.x * blockDim.x + threadIdx.x; i < n; i += stride) {
        const int j = __ldg(idx + i);

        // Issue all memory traffic up front for MLP.
        const float4 s  = __ldg(src + (size_t)i);
        const float4 c0 = __ldg(covs_src + 4 * (size_t)i + 0);
        const float4 c1 = __ldg(covs_src + 4 * (size_t)i + 1);
        const float4 c2 = __ldg(covs_src + 4 * (size_t)i + 2);
        const float4 tp = __ldg(tar + (size_t)j);
        const float4 d0 = __ldg(covs_tar + 4 * (size_t)j + 0);
        const float4 d1 = __ldg(covs_tar + 4 * (size_t)j + 1);
        const float4 d2 = __ldg(covs_tar + 4 * (size_t)j + 2);

        // transformed_src = src_row_vector @ T  (take xyz)
        const float tsx = s.x * t[0] + s.y * t[4] + s.z * t[8]  + s.w * t[12];
        const float tsy = s.x * t[1] + s.y * t[5] + s.z * t[9]  + s.w * t[13];
        const float tsz = s.x * t[2] + s.y * t[6] + s.z * t[10] + s.w * t[14];

        const float rx = tp.x - tsx;
        const float ry = tp.y - tsy;
        const float rz = tp.z - tsz;

        // B = R * C3 ; M = Ctar3 + B * R^T (symmetric), R[a][k] = t[4a+k]
        const float C00 = c0.x, C01 = c0.y, C02 = c0.z;
        const float C10 = c1.x, C11 = c1.y, C12 = c1.z;
        const float C20 = c2.x, C21 = c2.y, C22 = c2.z;

        float B[3][3];
        #pragma unroll
        for (int a = 0; a < 3; ++a) {
            const float r0 = t[4 * a + 0], r1 = t[4 * a + 1], r2 = t[4 * a + 2];
            B[a][0] = r0 * C00 + r1 * C10 + r2 * C20;
            B[a][1] = r0 * C01 + r1 * C11 + r2 * C21;
            B[a][2] = r0 * C02 + r1 * C12 + r2 * C22;
        }

        // Symmetric M = [a b c; b d e; c e f]
        const float ma = B[0][0] * t[0] + B[0][1] * t[1] + B[0][2] * t[2]  + d0.x;
        const float mb = B[0][0] * t[4] + B[0][1] * t[5] + B[0][2] * t[6]  + d0.y;
        const float mc = B[0][0] * t[8] + B[0][1] * t[9] + B[0][2] * t[10] + d0.z;
        const float md = B[1][0] * t[4] + B[1][1] * t[5] + B[1][2] * t[6]  + d1.y;
        const float me = B[1][0] * t[8] + B[1][1] * t[9] + B[1][2] * t[10] + d1.z;
        const float mf = B[2][0] * t[8] + B[2][1] * t[9] + B[2][2] * t[10] + d2.z;

        // maha = res^T adj(M) res / det(M)
        const float adj00 = md * mf - me * me;
        const float adj01 = mc * me - mb * mf;
        const float adj02 = mb * me - mc * md;
        const float det   = ma * adj00 + mb * adj01 + mc * adj02;
        const float adj11 = ma * mf - mc * mc;
        const float adj12 = mb * mc - ma * me;
        const float adj22 = ma * md - mb * mb;

        const float q =
            rx * (rx * adj00 + ry * adj01 + rz * adj02) +
            ry * (rx * adj01 + ry * adj11 + rz * adj12) +
            rz * (rx * adj02 + ry * adj12 + rz * adj22);

        acc += q / det;
    }

    acc *= scale;   // scale = 0.5 / N folded in

    // Warp reduce
    #pragma unroll
    for (int o = 16; o > 0; o >>= 1)
        acc += __shfl_down_sync(0xffffffffu, acc, o);

    __shared__ float ws[8];
    if ((threadIdx.x & 31) == 0) ws[threadIdx.x >> 5] = acc;
    __syncthreads();

    if (threadIdx.x < 8) {
        float v = ws[threadIdx.x];
        #pragma unroll
        for (int o = 4; o > 0; o >>= 1)
            v += __shfl_down_sync(0xffu, v, o);
        if (threadIdx.x == 0) atomicAdd(out, v);
    }
}

extern "C" void kernel_launch(void* const* d_in, const int* in_sizes, int n_in,
                              void* d_out, int out_size)
{
    const float*  T        = (const float*) d_in[0];
    const float4* src      = (const float4*)d_in[1];
    const float4* tar      = (const float4*)d_in[2];
    const float4* covs_src = (const float4*)d_in[3];
    const float4* covs_tar = (const float4*)d_in[4];
    const int*    idx      = (const int*)   d_in[5];
    float* out = (float*)d_out;

    const int n = in_sizes[5];          // N points
    const float scale = 0.5f / (float)n;

    gicp_zero_out<<<1, 32>>>(out);

    // One wave: 152 SMs x 8 CTAs/SM (256 thr, 32-40 regs -> 8 resident).
    const int tpb  = 256;
    const int grid = 152 * 8;
    gicp_kernel<<<grid, tpb>>>(T, src, tar, covs_src, covs_tar, idx, out, n, scale);
}

// round 13
// speedup vs baseline: 1.0887x; 1.0887x over previous
#include <cuda_runtime.h>
#include <cstddef>

// Inputs (metadata order):
//  0: transformation  float32  (4,4)
//  1: src_points      float32  (N,4)
//  2: tar_points      float32  (N,4)
//  3: covs_src        float32  (N,4,4)
//  4: covs_tar        float32  (N,4,4)
//  5: nearest_indices int32    (N,)
// Output: scalar float = 0.5 * mean(maha)
//
// Final form: HBM-bound gather+reduce at the measured roofline (~80% DRAM,
// ~6.37TB/s over ~449MB effective traffic). Campaign: L2 hints, target
// partitioning, index binning, launch fusion, 2pt/thread, and persistent
// grids all measured neutral or worse — occupancy (94%, 32 regs) is the
// binding resource for achieved bandwidth. This round: tpb 256->512 (same
// regs/occupancy, half the block-reduction tails).

__global__ void gicp_zero_out(float* out) {
    if (blockIdx.x == 0 && threadIdx.x == 0) out[0] = 0.0f;
}

__global__ __launch_bounds__(512) void gicp_kernel(
    const float*  __restrict__ T,         // 16 floats
    const float4* __restrict__ src,       // N rows (x,y,z,1)
    const float4* __restrict__ tar,       // N rows
    const float4* __restrict__ covs_src,  // N * 4 rows
    const float4* __restrict__ covs_tar,  // N * 4 rows
    const int*    __restrict__ idx,       // N
    float*        __restrict__ out,
    int n, float scale)
{
    const int i = blockIdx.x * blockDim.x + threadIdx.x;
    float acc = 0.0f;

    if (i < n) {
        // Broadcast load of the 4x4 transformation (L1 hit after warmup).
        float t[16];
        #pragma unroll
        for (int k = 0; k < 16; ++k) t[k] = __ldg(T + k);

        const int j = __ldg(idx + i);

        // Issue all memory traffic up front for MLP.
        const float4 s  = __ldg(src + (size_t)i);
        const float4 c0 = __ldg(covs_src + 4 * (size_t)i + 0);
        const float4 c1 = __ldg(covs_src + 4 * (size_t)i + 1);
        const float4 c2 = __ldg(covs_src + 4 * (size_t)i + 2);
        const float4 tp = __ldg(tar + (size_t)j);
        const float4 d0 = __ldg(covs_tar + 4 * (size_t)j + 0);
        const float4 d1 = __ldg(covs_tar + 4 * (size_t)j + 1);
        const float4 d2 = __ldg(covs_tar + 4 * (size_t)j + 2);

        // transformed_src = src_row_vector @ T  (take xyz)
        const float tsx = s.x * t[0] + s.y * t[4] + s.z * t[8]  + s.w * t[12];
        const float tsy = s.x * t[1] + s.y * t[5] + s.z * t[9]  + s.w * t[13];
        const float tsz = s.x * t[2] + s.y * t[6] + s.z * t[10] + s.w * t[14];

        const float rx = tp.x - tsx;
        const float ry = tp.y - tsy;
        const float rz = tp.z - tsz;

        // B = R * C3 ; M = Ctar3 + B * R^T (symmetric), R[a][k] = t[4a+k]
        const float C00 = c0.x, C01 = c0.y, C02 = c0.z;
        const float C10 = c1.x, C11 = c1.y, C12 = c1.z;
        const float C20 = c2.x, C21 = c2.y, C22 = c2.z;

        float B[3][3];
        #pragma unroll
        for (int a = 0; a < 3; ++a) {
            const float r0 = t[4 * a + 0], r1 = t[4 * a + 1], r2 = t[4 * a + 2];
            B[a][0] = r0 * C00 + r1 * C10 + r2 * C20;
            B[a][1] = r0 * C01 + r1 * C11 + r2 * C21;
            B[a][2] = r0 * C02 + r1 * C12 + r2 * C22;
        }

        // Symmetric M = [a b c; b d e; c e f]
        const float ma = B[0][0] * t[0] + B[0][1] * t[1] + B[0][2] * t[2]  + d0.x;
        const float mb = B[0][0] * t[4] + B[0][1] * t[5] + B[0][2] * t[6]  + d0.y;
        const float mc = B[0][0] * t[8] + B[0][1] * t[9] + B[0][2] * t[10] + d0.z;
        const float md = B[1][0] * t[4] + B[1][1] * t[5] + B[1][2] * t[6]  + d1.y;
        const float me = B[1][0] * t[8] + B[1][1] * t[9] + B[1][2] * t[10] + d1.z;
        const float mf = B[2][0] * t[8] + B[2][1] * t[9] + B[2][2] * t[10] + d2.z;

        // maha = res^T adj(M) res / det(M)
        const float adj00 = md * mf - me * me;
        const float adj01 = mc * me - mb * mf;
        const float adj02 = mb * me - mc * md;
        const float det   = ma * adj00 + mb * adj01 + mc * adj02;
        const float adj11 = ma * mf - mc * mc;
        const float adj12 = mb * mc - ma * me;
        const float adj22 = ma * md - mb * mb;

        const float q =
            rx * (rx * adj00 + ry * adj01 + rz * adj02) +
            ry * (rx * adj01 + ry * adj11 + rz * adj12) +
            rz * (rx * adj02 + ry * adj12 + rz * adj22);

        acc = (q / det) * scale;   // scale = 0.5 / N folded in
    }

    // Warp reduce
    #pragma unroll
    for (int o = 16; o > 0; o >>= 1)
        acc += __shfl_down_sync(0xffffffffu, acc, o);

    __shared__ float ws[16];
    if ((threadIdx.x & 31) == 0) ws[threadIdx.x >> 5] = acc;
    __syncthreads();

    if (threadIdx.x < 16) {
        float v = ws[threadIdx.x];
        #pragma unroll
        for (int o = 8; o > 0; o >>= 1)
            v += __shfl_down_sync(0xffffu, v, o);
        if (threadIdx.x == 0) atomicAdd(out, v);
    }
}

extern "C" void kernel_launch(void* const* d_in, const int* in_sizes, int n_in,
                              void* d_out, int out_size)
{
    const float*  T        = (const float*) d_in[0];
    const float4* src      = (const float4*)d_in[1];
    const float4* tar      = (const float4*)d_in[2];
    const float4* covs_src = (const float4*)d_in[3];
    const float4* covs_tar = (const float4*)d_in[4];
    const int*    idx      = (const int*)   d_in[5];
    float* out = (float*)d_out;

    const int n = in_sizes[5];          // N points
    const float scale = 0.5f / (float)n;

    gicp_zero_out<<<1, 32>>>(out);

    const int tpb = 512;
    const int grid = (n + tpb - 1) / tpb;
    gicp_kernel<<<grid, tpb>>>(T, src, tar, covs_src, covs_tar, idx, out, n, scale);
}